// round 1
// baseline (speedup 1.0000x reference)
#include <cuda_runtime.h>

#define NQ 4096
#define CAP 16

// Scratch (__device__ globals; no allocations allowed)
__device__ float4 g_pt4[NQ];          // {x, y, end_score, jun_score}
__device__ int    g_rank[2][NQ];      // output slot per channel
__device__ int    g_cnt[2][NQ];       // earlier-neighbor counts
__device__ int    g_nbr[2][NQ * CAP]; // earlier-neighbor lists

// ---------------------------------------------------------------------------
// K1: softmax over 3 classes, scale points, write out[:,0..2]
// ---------------------------------------------------------------------------
__global__ void k1_prep(const float* __restrict__ logits,
                        const float* __restrict__ boxes,
                        const float* __restrict__ tsz,
                        float* __restrict__ out) {
    int i = blockIdx.x * blockDim.x + threadIdx.x;
    if (i >= NQ) return;
    float l0 = logits[3 * i + 0];
    float l1 = logits[3 * i + 1];
    float l2 = logits[3 * i + 2];
    float m  = fmaxf(l0, fmaxf(l1, l2));
    float e0 = expf(l0 - m);
    float e1 = expf(l1 - m);
    float e2 = expf(l2 - m);
    float s  = e0 + e1 + e2;
    float p0 = e0 / s;   // end_pt prob
    float p1 = e1 / s;   // junction_pt prob
    float p2 = e2 / s;   // background prob

    float x = boxes[2 * i + 0] * tsz[0];
    float y = boxes[2 * i + 1] * tsz[1];

    out[5 * i + 0] = 1.0f - p2;
    out[5 * i + 1] = x;
    out[5 * i + 2] = y;
    g_pt4[i] = make_float4(x, y, p0, p1);
}

// ---------------------------------------------------------------------------
// K2: all-pairs pass. For each point i compute, per channel:
//   rank(i)  = #{ j : earlier(j,i) }      (output slot — replaces the sort)
//   nbrs(i)  = { j : earlier(j,i) && dist2 < 25 }
// earlier(j,i) = (s_j > s_i) || (s_j == s_i && j < i)   (stable-sort order)
// ---------------------------------------------------------------------------
__global__ void k2_pairs() {
    __shared__ float4 tile[256];
    int i = blockIdx.x * 256 + threadIdx.x;
    float4 me = g_pt4[i];

    int rE = 0, rJ = 0, cE = 0, cJ = 0;
    int nbE[CAP], nbJ[CAP];

    for (int t = 0; t < NQ; t += 256) {
        tile[threadIdx.x] = g_pt4[t + threadIdx.x];
        __syncthreads();
#pragma unroll 8
        for (int jj = 0; jj < 256; jj++) {
            float4 q = tile[jj];           // broadcast LDS.128 (all lanes same addr)
            int j = t + jj;
            float dx = me.x - q.x;
            float dy = me.y - q.y;
            // match non-contracted dx*dx + dy*dy evaluation
            float d2 = __fadd_rn(__fmul_rn(dx, dx), __fmul_rn(dy, dy));
            bool close = d2 < 25.0f;
            bool eE = (q.z > me.z) || ((q.z == me.z) && (j < i));
            bool eJ = (q.w > me.w) || ((q.w == me.w) && (j < i));
            rE += eE;
            rJ += eJ;
            if (close && eE) { if (cE < CAP) nbE[cE] = j; cE++; }
            if (close && eJ) { if (cJ < CAP) nbJ[cJ] = j; cJ++; }
        }
        __syncthreads();
    }

    g_rank[0][i] = rE;
    g_rank[1][i] = rJ;
    g_cnt[0][i]  = cE;
    g_cnt[1][i]  = cJ;
    int mE = cE < CAP ? cE : CAP;
    int mJ = cJ < CAP ? cJ : CAP;
    for (int k = 0; k < mE; k++) g_nbr[0][i * CAP + k] = nbE[k];
    for (int k = 0; k < mJ; k++) g_nbr[1][i * CAP + k] = nbJ[k];
}

// ---------------------------------------------------------------------------
// K3: greedy-NMS fixpoint.  keep[i] = valid[i] && no kept earlier-neighbor.
// Dependency graph is a DAG (earlier() is a strict total order), so chaotic
// parallel sweeps separated by __syncthreads converge to the unique greedy
// fixpoint in <= max-chain-depth sweeps (~3 on this data).
// Then scatter: out[rank(i)*5 + 3/4] = keep ? score : 0.
// ---------------------------------------------------------------------------
__global__ void k3_resolve(float* __restrict__ out) {
    __shared__ unsigned char keep[2][NQ];
    __shared__ int changed;
    int tid = threadIdx.x;

    for (int u = tid; u < NQ; u += blockDim.x) {
        float4 p = g_pt4[u];
        keep[0][u] = (p.z >= 0.05f) ? 1 : 0;
        keep[1][u] = (p.w >= 0.05f) ? 1 : 0;
    }
    __syncthreads();

    while (true) {
        if (tid == 0) changed = 0;
        __syncthreads();

        for (int ch = 0; ch < 2; ch++) {
            for (int u = tid; u < NQ; u += blockDim.x) {
                float4 me = g_pt4[u];
                float si = (ch == 0) ? me.z : me.w;
                bool nk = (si >= 0.05f);
                if (nk) {
                    int c = g_cnt[ch][u];
                    if (c <= CAP) {
                        for (int k = 0; k < c; k++) {
                            if (keep[ch][g_nbr[ch][u * CAP + k]]) { nk = false; break; }
                        }
                    } else {
                        // overflow fallback: rescan all points (never hit on this data)
                        for (int j = 0; j < NQ && nk; j++) {
                            float4 q = g_pt4[j];
                            float sj = (ch == 0) ? q.z : q.w;
                            bool e = (sj > si) || ((sj == si) && (j < u));
                            if (e && keep[ch][j]) {
                                float dx = me.x - q.x, dy = me.y - q.y;
                                float d2 = __fadd_rn(__fmul_rn(dx, dx), __fmul_rn(dy, dy));
                                if (d2 < 25.0f) nk = false;
                            }
                        }
                    }
                }
                if (nk != (bool)keep[ch][u]) {
                    keep[ch][u] = nk ? 1 : 0;
                    changed = 1;
                }
            }
        }
        __syncthreads();
        if (changed == 0) break;
        __syncthreads();   // all threads saw changed before tid0 resets it
    }

    // scatter NMS outputs to sorted slots
    for (int u = tid; u < NQ; u += blockDim.x) {
        float4 p = g_pt4[u];
        out[g_rank[0][u] * 5 + 3] = keep[0][u] ? p.z : 0.0f;
        out[g_rank[1][u] * 5 + 4] = keep[1][u] ? p.w : 0.0f;
    }
}

// ---------------------------------------------------------------------------
extern "C" void kernel_launch(void* const* d_in, const int* in_sizes, int n_in,
                              void* d_out, int out_size) {
    const float* logits = (const float*)d_in[0];  // [1,4096,3]
    const float* boxes  = (const float*)d_in[1];  // [1,4096,2]
    // d_in[2] = pred_gids (unused)
    const float* tsz    = (const float*)d_in[3];  // [1,2]
    float* out          = (float*)d_out;          // [1,4096,5]

    k1_prep<<<NQ / 256, 256>>>(logits, boxes, tsz, out);
    k2_pairs<<<NQ / 256, 256>>>();
    k3_resolve<<<1, 1024>>>(out);
}

// round 2
// speedup vs baseline: 5.1399x; 5.1399x over previous
#include <cuda_runtime.h>

#define NQ 4096
#define CAP 16
#define TI 256   // i-tile (threads per block)
#define TJ 256   // j-tile

// Scratch (__device__ globals; no allocations allowed)
__device__ float4             g_pt4[NQ];          // {x, y, end_score, jun_score}
__device__ float2             g_xy[NQ];           // {x, y}
__device__ unsigned long long g_keyE[NQ];         // (score_bits<<12) | (4095-i)
__device__ unsigned long long g_keyJ[NQ];
__device__ int                g_rank[2][NQ];      // output slot per channel (atomic sum)
__device__ int                g_cnt[2][NQ];       // earlier-neighbor counts (atomic)
__device__ int                g_nbr[2][NQ * CAP]; // earlier-neighbor lists

// ---------------------------------------------------------------------------
// K1: softmax over 3 classes, scale points, write out[:,0..2], build keys,
//     zero the atomic accumulators.
// ---------------------------------------------------------------------------
__global__ void k1_prep(const float* __restrict__ logits,
                        const float* __restrict__ boxes,
                        const float* __restrict__ tsz,
                        float* __restrict__ out) {
    int i = blockIdx.x * blockDim.x + threadIdx.x;
    if (i >= NQ) return;
    float l0 = logits[3 * i + 0];
    float l1 = logits[3 * i + 1];
    float l2 = logits[3 * i + 2];
    float m  = fmaxf(l0, fmaxf(l1, l2));
    float e0 = expf(l0 - m);
    float e1 = expf(l1 - m);
    float e2 = expf(l2 - m);
    float s  = e0 + e1 + e2;
    float p0 = e0 / s;   // end_pt prob
    float p1 = e1 / s;   // junction_pt prob
    float p2 = e2 / s;   // background prob

    float x = boxes[2 * i + 0] * tsz[0];
    float y = boxes[2 * i + 1] * tsz[1];

    out[5 * i + 0] = 1.0f - p2;
    out[5 * i + 1] = x;
    out[5 * i + 2] = y;
    g_pt4[i] = make_float4(x, y, p0, p1);
    g_xy[i]  = make_float2(x, y);
    // softmax probs are positive finite => IEEE bit pattern is order-monotone.
    // earlier(j,i) = (s_j > s_i) || (s_j == s_i && j < i)  <=>  key_j > key_i
    g_keyE[i] = (((unsigned long long)__float_as_uint(p0)) << 12) |
                (unsigned long long)(NQ - 1 - i);
    g_keyJ[i] = (((unsigned long long)__float_as_uint(p1)) << 12) |
                (unsigned long long)(NQ - 1 - i);
    g_rank[0][i] = 0; g_rank[1][i] = 0;
    g_cnt[0][i]  = 0; g_cnt[1][i]  = 0;
}

// ---------------------------------------------------------------------------
// K2: all-pairs pass, 2-D tiled: block (bx,by) handles i in bx-tile vs j in
// by-tile. Per channel accumulates rank(i) = #earlier(j,i) via atomicAdd and
// appends earlier-neighbors within dist<5 via atomic slot grab.
// ---------------------------------------------------------------------------
__global__ void k2_pairs() {
    __shared__ float2             sxy[TJ];
    __shared__ unsigned long long skE[TJ];
    __shared__ unsigned long long skJ[TJ];

    int i  = blockIdx.x * TI + threadIdx.x;
    int j0 = blockIdx.y * TJ;

    // cooperative tile load
    sxy[threadIdx.x] = g_xy[j0 + threadIdx.x];
    skE[threadIdx.x] = g_keyE[j0 + threadIdx.x];
    skJ[threadIdx.x] = g_keyJ[j0 + threadIdx.x];
    __syncthreads();

    float2             me = g_xy[i];
    unsigned long long kE = g_keyE[i];
    unsigned long long kJ = g_keyJ[i];

    int rE = 0, rJ = 0;

#pragma unroll 8
    for (int jj = 0; jj < TJ; jj++) {
        float2 q = sxy[jj];                       // broadcast LDS
        unsigned long long qE = skE[jj];
        unsigned long long qJ = skJ[jj];
        float dx = me.x - q.x;
        float dy = me.y - q.y;
        // match non-contracted dx*dx + dy*dy evaluation
        float d2 = __fadd_rn(__fmul_rn(dx, dx), __fmul_rn(dy, dy));
        bool eE = qE > kE;
        bool eJ = qJ > kJ;
        rE += eE;
        rJ += eJ;
        if (d2 < 25.0f) {                          // rare (~0.03% of pairs)
            int j = j0 + jj;
            if (eE) {
                int s = atomicAdd(&g_cnt[0][i], 1);
                if (s < CAP) g_nbr[0][i * CAP + s] = j;
            }
            if (eJ) {
                int s = atomicAdd(&g_cnt[1][i], 1);
                if (s < CAP) g_nbr[1][i * CAP + s] = j;
            }
        }
    }

    atomicAdd(&g_rank[0][i], rE);
    atomicAdd(&g_rank[1][i], rJ);
}

// ---------------------------------------------------------------------------
// K3: greedy-NMS fixpoint.  keep[i] = valid[i] && no kept earlier-neighbor.
// The earlier() relation is a strict total order => dependency DAG => chaotic
// parallel sweeps converge to the unique greedy fixpoint (order of neighbor
// lists irrelevant). Then scatter out[rank(i)*5 + 3/4].
// ---------------------------------------------------------------------------
__global__ void k3_resolve(float* __restrict__ out) {
    __shared__ unsigned char keep[2][NQ];
    __shared__ int changed;
    int tid = threadIdx.x;

    for (int u = tid; u < NQ; u += blockDim.x) {
        float4 p = g_pt4[u];
        keep[0][u] = (p.z >= 0.05f) ? 1 : 0;
        keep[1][u] = (p.w >= 0.05f) ? 1 : 0;
    }
    __syncthreads();

    while (true) {
        if (tid == 0) changed = 0;
        __syncthreads();

        for (int ch = 0; ch < 2; ch++) {
            for (int u = tid; u < NQ; u += blockDim.x) {
                float4 me = g_pt4[u];
                float si = (ch == 0) ? me.z : me.w;
                bool nk = (si >= 0.05f);
                if (nk) {
                    int c = g_cnt[ch][u];
                    if (c <= CAP) {
                        for (int k = 0; k < c; k++) {
                            if (keep[ch][g_nbr[ch][u * CAP + k]]) { nk = false; break; }
                        }
                    } else {
                        // overflow fallback: rescan all points (never hit on this data)
                        unsigned long long ku = (ch == 0) ? g_keyE[u] : g_keyJ[u];
                        for (int j = 0; j < NQ && nk; j++) {
                            unsigned long long kj = (ch == 0) ? g_keyE[j] : g_keyJ[j];
                            if (kj > ku && keep[ch][j]) {
                                float4 q = g_pt4[j];
                                float dx = me.x - q.x, dy = me.y - q.y;
                                float d2 = __fadd_rn(__fmul_rn(dx, dx), __fmul_rn(dy, dy));
                                if (d2 < 25.0f) nk = false;
                            }
                        }
                    }
                }
                if (nk != (bool)keep[ch][u]) {
                    keep[ch][u] = nk ? 1 : 0;
                    changed = 1;
                }
            }
        }
        __syncthreads();
        if (changed == 0) break;
        __syncthreads();   // all threads saw changed before tid0 resets it
    }

    // scatter NMS outputs to sorted slots
    for (int u = tid; u < NQ; u += blockDim.x) {
        float4 p = g_pt4[u];
        out[g_rank[0][u] * 5 + 3] = keep[0][u] ? p.z : 0.0f;
        out[g_rank[1][u] * 5 + 4] = keep[1][u] ? p.w : 0.0f;
    }
}

// ---------------------------------------------------------------------------
extern "C" void kernel_launch(void* const* d_in, const int* in_sizes, int n_in,
                              void* d_out, int out_size) {
    const float* logits = (const float*)d_in[0];  // [1,4096,3]
    const float* boxes  = (const float*)d_in[1];  // [1,4096,2]
    // d_in[2] = pred_gids (unused)
    const float* tsz    = (const float*)d_in[3];  // [1,2]
    float* out          = (float*)d_out;          // [1,4096,5]

    k1_prep<<<NQ / 256, 256>>>(logits, boxes, tsz, out);
    dim3 g2(NQ / TI, NQ / TJ);
    k2_pairs<<<g2, TI>>>();
    k3_resolve<<<1, 1024>>>(out);
}